// round 12
// baseline (speedup 1.0000x reference)
#include <cuda_runtime.h>
#include <cuda_fp16.h>
#include <math.h>
#include <stdint.h>

#define B_      8
#define N_      1024
#define H_      1024
#define HEADS_  16
#define DH_     64
#define M_      (B_ * N_)          // 8192
#define CTXN_   ((size_t)M_ * H_)  // 8388608

// -------- scratch (device globals; no allocation allowed) --------
__device__ __half g_Xh[(size_t)M_ * H_];                 // hidden in half
__device__ __half g_Wh[4][(size_t)H_ * H_];              // Wq,Wk,Wv,Wo in half
__device__ __half g_Qh[(size_t)B_ * HEADS_ * N_ * DH_];  // head-split [bh][n][64]
__device__ __half g_Kh[(size_t)B_ * HEADS_ * N_ * DH_];
__device__ __half g_Vh[(size_t)B_ * HEADS_ * N_ * DH_];
__device__ __half g_ctxh[(size_t)M_ * H_];
__device__ float  g_y[(size_t)M_ * H_];
__device__ unsigned g_maskbits[(size_t)B_ * N_ * (N_ / 32)];   // 1MB bitmask

// ---------------- mma / ldmatrix helpers ----------------
__device__ __forceinline__ void mma_f16(float* d, const uint32_t* a, const uint32_t* b, const float* c) {
    asm volatile(
        "mma.sync.aligned.m16n8k16.row.col.f32.f16.f16.f32 "
        "{%0,%1,%2,%3}, {%4,%5,%6,%7}, {%8,%9}, {%10,%11,%12,%13};\n"
        : "=f"(d[0]), "=f"(d[1]), "=f"(d[2]), "=f"(d[3])
        : "r"(a[0]), "r"(a[1]), "r"(a[2]), "r"(a[3]),
          "r"(b[0]), "r"(b[1]),
          "f"(c[0]), "f"(c[1]), "f"(c[2]), "f"(c[3]));
}

__device__ __forceinline__ void ldsm4(uint32_t* r, uint32_t addr) {
    asm volatile("ldmatrix.sync.aligned.m8n8.x4.shared.b16 {%0,%1,%2,%3}, [%4];\n"
        : "=r"(r[0]), "=r"(r[1]), "=r"(r[2]), "=r"(r[3]) : "r"(addr));
}
__device__ __forceinline__ void ldsm4t(uint32_t* r, uint32_t addr) {
    asm volatile("ldmatrix.sync.aligned.m8n8.x4.trans.shared.b16 {%0,%1,%2,%3}, [%4];\n"
        : "=r"(r[0]), "=r"(r[1]), "=r"(r[2]), "=r"(r[3]) : "r"(addr));
}
__device__ __forceinline__ uint32_t packh2(float lo, float hi) {
    __half2 h = __floats2half2_rn(lo, hi);
    return *(uint32_t*)&h;
}
__device__ __forceinline__ uint32_t smem_u32(const void* p) {
    return (uint32_t)__cvta_generic_to_shared(p);
}

// ===================================================================
// Kernel A: convert X + 4 weights to half. 8 elems/thread.
// ===================================================================
__global__ __launch_bounds__(256) void cvt_inputs(
    const float* __restrict__ hs,
    const float* __restrict__ wq, const float* __restrict__ wk,
    const float* __restrict__ wv, const float* __restrict__ wo)
{
    size_t gid = ((size_t)blockIdx.x * 256 + threadIdx.x) * 8;
    const float* src;
    __half* dst;
    size_t off;
    if (gid < CTXN_) { src = hs; dst = g_Xh; off = gid; }
    else {
        size_t r = gid - CTXN_;
        int seg = (int)(r >> 20);
        off = r & ((1u << 20) - 1);
        src = (seg == 0) ? wq : (seg == 1) ? wk : (seg == 2) ? wv : wo;
        dst = g_Wh[seg];
    }
    float4 a = *(const float4*)(src + off);
    float4 b = *(const float4*)(src + off + 4);
    uint4 u;
    u.x = packh2(a.x, a.y); u.y = packh2(a.z, a.w);
    u.z = packh2(b.x, b.y); u.w = packh2(b.z, b.w);
    *(uint4*)(dst + off) = u;
}

// ===================================================================
// Kernel B: pack role_mask into bitmask.
// ===================================================================
__global__ __launch_bounds__(256) void pack_mask(const int* __restrict__ mask)
{
    const int gid = blockIdx.x * 256 + threadIdx.x;
    const int4* p = (const int4*)(mask + (size_t)gid * 32);
    uint32_t bits = 0;
#pragma unroll
    for (int i = 0; i < 8; i++) {
        int4 v = p[i];
        bits |= (uint32_t)(v.x != 0) << (i * 4 + 0);
        bits |= (uint32_t)(v.y != 0) << (i * 4 + 1);
        bits |= (uint32_t)(v.z != 0) << (i * 4 + 2);
        bits |= (uint32_t)(v.w != 0) << (i * 4 + 3);
    }
    g_maskbits[gid] = bits;
}

// ===================================================================
// fp16 tensor-core GEMM: 128x128 tile, BK=16, 8 warps (2x4), warp 64x32.
// MODE 0: QKV (z selects W/bias/out), head-split half output.
// MODE 1: out proj: acc + bias + residual -> g_y (fp32).
// ===================================================================
#define AS_ 24
#define BS_ 136
#define A_BUF_B (128 * AS_ * 2)   // 6144 bytes
#define B_BUF_B (16 * BS_ * 2)    // 4352 bytes

template<int MODE>
__global__ __launch_bounds__(256, 2) void gemm_h(
    const float* __restrict__ b0p, const float* __restrict__ b1p,
    const float* __restrict__ b2p, const float* __restrict__ hidden)
{
    __shared__ __align__(16) __half sA[2][128 * AS_];
    __shared__ __align__(16) __half sB[2][16 * BS_];

    const __half* A;
    const __half* W;
    const float* bias;
    if (MODE == 0) {
        A = g_Xh;
        W = g_Wh[blockIdx.z];
        bias = (blockIdx.z == 0) ? b0p : (blockIdx.z == 1) ? b1p : b2p;
    } else {
        A = g_ctxh;
        W = g_Wh[3];
        bias = b0p;
    }

    const int tid = threadIdx.x;
    const int warp = tid >> 5, lane = tid & 31;
    const int g = lane >> 2, q = lane & 3;
    const int wm = (warp >> 2) * 64, wn = (warp & 3) * 32;
    const int m0 = blockIdx.y * 128, n0 = blockIdx.x * 128;

    const int arow = tid >> 1, acol = (tid & 1) * 8;
    const int brow = tid >> 4, bcol = (tid & 15) * 8;

    uint4 ra, rb;
    auto LDG = [&](int k0) {
        ra = *(const uint4*)&A[(size_t)(m0 + arow) * H_ + k0 + acol];
        rb = *(const uint4*)&W[(size_t)(k0 + brow) * H_ + n0 + bcol];
    };
    auto STS = [&](int st) {
        *(uint4*)&sA[st][arow * AS_ + acol] = ra;
        *(uint4*)&sB[st][brow * BS_ + bcol] = rb;
    };

    const uint32_t sAb = smem_u32(&sA[0][0]);
    const uint32_t sBb = smem_u32(&sB[0][0]);
    const int la = lane & 15, lb = lane >> 4;
    const uint32_t aoff = ((wm + la) * AS_ + lb * 8) * 2;
    const uint32_t boff = (la * BS_ + wn + lb * 8) * 2;

    float acc[4][4][4];
#pragma unroll
    for (int mt = 0; mt < 4; mt++)
#pragma unroll
        for (int nt = 0; nt < 4; nt++)
#pragma unroll
            for (int j = 0; j < 4; j++) acc[mt][nt][j] = 0.f;

    LDG(0); STS(0);
    __syncthreads();

    for (int kt = 0; kt < 64; kt++) {
        const int cur = kt & 1;
        if (kt < 63) LDG((kt + 1) * 16);

        const uint32_t bufA = sAb + cur * A_BUF_B;
        const uint32_t bufB = sBb + cur * B_BUF_B;
        uint32_t a[4][4], b[2][4];
#pragma unroll
        for (int mt = 0; mt < 4; mt++)
            ldsm4(a[mt], bufA + aoff + mt * (16 * AS_ * 2));
#pragma unroll
        for (int n2 = 0; n2 < 2; n2++)
            ldsm4t(b[n2], bufB + boff + n2 * 32);
#pragma unroll
        for (int mt = 0; mt < 4; mt++)
#pragma unroll
            for (int nt = 0; nt < 4; nt++)
                mma_f16(acc[mt][nt], a[mt], &b[nt >> 1][(nt & 1) * 2], acc[mt][nt]);

        if (kt < 63) STS(cur ^ 1);
        __syncthreads();
    }

    // ---------------- epilogue ----------------
    if (MODE == 0) {
        __half* out = (blockIdx.z == 0) ? g_Qh : (blockIdx.z == 1) ? g_Kh : g_Vh;
        const int bi = m0 >> 10;
#pragma unroll
        for (int mt = 0; mt < 4; mt++) {
            const int row = m0 + wm + mt * 16 + g;
            const int n = row & 1023;
#pragma unroll
            for (int nt = 0; nt < 4; nt++) {
                const int col = n0 + wn + nt * 8 + 2 * q;
                const int head = col >> 6, d = col & 63;
                const float bb0 = __ldg(&bias[col]), bb1 = __ldg(&bias[col + 1]);
                __half2 v0 = __floats2half2_rn(acc[mt][nt][0] + bb0, acc[mt][nt][1] + bb1);
                __half2 v1 = __floats2half2_rn(acc[mt][nt][2] + bb0, acc[mt][nt][3] + bb1);
                *(__half2*)&out[(((size_t)bi * HEADS_ + head) * N_ + n) * DH_ + d] = v0;
                *(__half2*)&out[(((size_t)bi * HEADS_ + head) * N_ + n + 8) * DH_ + d] = v1;
            }
        }
    } else {
#pragma unroll
        for (int mt = 0; mt < 4; mt++) {
            const int row = m0 + wm + mt * 16 + g;
#pragma unroll
            for (int nt = 0; nt < 4; nt++) {
                const int col = n0 + wn + nt * 8 + 2 * q;
                const float bb0 = __ldg(&bias[col]), bb1 = __ldg(&bias[col + 1]);
                size_t o0 = (size_t)row * H_ + col;
                size_t o1 = (size_t)(row + 8) * H_ + col;
                float2 h0 = *(const float2*)&hidden[o0];
                float2 h1 = *(const float2*)&hidden[o1];
                *(float2*)&g_y[o0] = make_float2(acc[mt][nt][0] + bb0 + h0.x, acc[mt][nt][1] + bb1 + h0.y);
                *(float2*)&g_y[o1] = make_float2(acc[mt][nt][2] + bb0 + h1.x, acc[mt][nt][3] + bb1 + h1.y);
            }
        }
    }
}

// ===================================================================
// fp16 flash attention. q-tile 128, 8 warps (16 q-rows each), k-chunk 64.
// P C-frags repack directly into A-frags (no shuffles).
// ===================================================================
#define QS_ 72
__global__ __launch_bounds__(256, 2) void attn_h()
{
    __shared__ __align__(16) __half sQ[128 * QS_];
    __shared__ __align__(16) __half sK[64 * QS_];
    __shared__ __align__(16) __half sV[64 * QS_];

    const int tid = threadIdx.x;
    const int warp = tid >> 5, lane = tid & 31;
    const int g = lane >> 2, q = lane & 3;
    const int wq = warp * 16;

    const int bh = blockIdx.y;
    const int b = bh >> 4, h = bh & 15;
    const int q0 = blockIdx.x * 128;

    const __half* Qg = g_Qh + (size_t)bh * N_ * DH_;
    const __half* Kg = g_Kh + (size_t)bh * N_ * DH_;
    const __half* Vg = g_Vh + (size_t)bh * N_ * DH_;

    const int lrow = tid >> 3, lcol = (tid & 7) * 8;

    // Q tile 128x64
#pragma unroll
    for (int i = 0; i < 4; i++) {
        int r = i * 32 + lrow;
        uint4 v = *(const uint4*)&Qg[(size_t)(q0 + r) * DH_ + lcol];
        *(uint4*)&sQ[r * QS_ + lcol] = v;
    }
    auto loadKV = [&](int k0) {
#pragma unroll
        for (int i = 0; i < 2; i++) {
            int r = i * 32 + lrow;
            uint4 kv = *(const uint4*)&Kg[(size_t)(k0 + r) * DH_ + lcol];
            *(uint4*)&sK[r * QS_ + lcol] = kv;
            uint4 vv = *(const uint4*)&Vg[(size_t)(k0 + r) * DH_ + lcol];
            *(uint4*)&sV[r * QS_ + lcol] = vv;
        }
    };
    loadKV(0);
    __syncthreads();

    const uint32_t sQb = smem_u32(sQ), sKb = smem_u32(sK), sVb = smem_u32(sV);
    const int la = lane & 15, lb = lane >> 4;

    // Q frags once (constant over k-loop)
    uint32_t aq[4][4];
    {
        const uint32_t base = sQb + ((wq + la) * QS_ + lb * 8) * 2;
#pragma unroll
        for (int ks = 0; ks < 4; ks++) ldsm4(aq[ks], base + ks * 32);
    }

    const int kla = (lane >> 4) * 8 + (lane & 7);        // K frag row part
    const int klb = ((lane >> 3) & 1) * 8;               // K frag col part
    const int vla = ((lane >> 3) & 1) * 8 + (lane & 7);  // V frag row part
    const int vlb = (lane >> 4) * 8;                     // V frag col part
    const uint32_t koff = sKb + (kla * QS_ + klb) * 2;
    const uint32_t voff = sVb + (vla * QS_) * 2;

    const uint32_t* mrow0 = &g_maskbits[((size_t)(b << 10) + q0 + wq + g) * 32];
    const uint32_t* mrow1 = mrow0 + 8 * 32;

    float m0v = -INFINITY, m1v = -INFINITY, l0 = 0.f, l1 = 0.f;
    float o[8][4];
#pragma unroll
    for (int dt = 0; dt < 8; dt++)
#pragma unroll
        for (int j = 0; j < 4; j++) o[dt][j] = 0.f;

    for (int c = 0; c < 16; c++) {
        const int k0 = c * 64;
        if (c > 0) {
            __syncthreads();
            loadKV(k0);
            __syncthreads();
        }
        const int kw = k0 >> 5;
        const uint32_t w0a = __ldg(mrow0 + kw), w0b = __ldg(mrow0 + kw + 1);
        const uint32_t w1a = __ldg(mrow1 + kw), w1b = __ldg(mrow1 + kw + 1);

        // ---- S = Q K^T ----
        float sc[8][4];
#pragma unroll
        for (int nt = 0; nt < 8; nt++)
#pragma unroll
            for (int j = 0; j < 4; j++) sc[nt][j] = 0.f;

#pragma unroll
        for (int ks = 0; ks < 4; ks++) {
#pragma unroll
            for (int kg = 0; kg < 4; kg++) {
                uint32_t kb[4];
                ldsm4(kb, koff + (kg * 16 * QS_ + ks * 16) * 2);
                mma_f16(sc[2 * kg],     aq[ks], &kb[0], sc[2 * kg]);
                mma_f16(sc[2 * kg + 1], aq[ks], &kb[2], sc[2 * kg + 1]);
            }
        }

        // ---- mask + online softmax ----
        float mx0 = -INFINITY, mx1 = -INFINITY;
#pragma unroll
        for (int nt = 0; nt < 8; nt++) {
            const uint32_t ws0 = (nt < 4) ? w0a : w0b;
            const uint32_t ws1 = (nt < 4) ? w1a : w1b;
            const int bb = (nt & 3) * 8 + 2 * q;
            sc[nt][0] = ((ws0 >> bb) & 1u)       ? sc[nt][0] * 0.125f : -1e9f;
            sc[nt][1] = ((ws0 >> (bb + 1)) & 1u) ? sc[nt][1] * 0.125f : -1e9f;
            sc[nt][2] = ((ws1 >> bb) & 1u)       ? sc[nt][2] * 0.125f : -1e9f;
            sc[nt][3] = ((ws1 >> (bb + 1)) & 1u) ? sc[nt][3] * 0.125f : -1e9f;
            mx0 = fmaxf(mx0, fmaxf(sc[nt][0], sc[nt][1]));
            mx1 = fmaxf(mx1, fmaxf(sc[nt][2], sc[nt][3]));
        }
        mx0 = fmaxf(mx0, __shfl_xor_sync(0xffffffffu, mx0, 1));
        mx0 = fmaxf(mx0, __shfl_xor_sync(0xffffffffu, mx0, 2));
        mx1 = fmaxf(mx1, __shfl_xor_sync(0xffffffffu, mx1, 1));
        mx1 = fmaxf(mx1, __shfl_xor_sync(0xffffffffu, mx1, 2));

        const float mn0 = fmaxf(m0v, mx0);
        const float mn1 = fmaxf(m1v, mx1);
        float sum0 = 0.f, sum1 = 0.f;
#pragma unroll
        for (int nt = 0; nt < 8; nt++) {
            sc[nt][0] = __expf(sc[nt][0] - mn0);
            sc[nt][1] = __expf(sc[nt][1] - mn0);
            sc[nt][2] = __expf(sc[nt][2] - mn1);
            sc[nt][3] = __expf(sc[nt][3] - mn1);
            sum0 += sc[nt][0] + sc[nt][1];
            sum1 += sc[nt][2] + sc[nt][3];
        }
        sum0 += __shfl_xor_sync(0xffffffffu, sum0, 1);
        sum0 += __shfl_xor_sync(0xffffffffu, sum0, 2);
        sum1 += __shfl_xor_sync(0xffffffffu, sum1, 1);
        sum1 += __shfl_xor_sync(0xffffffffu, sum1, 2);

        const float al0 = __expf(m0v - mn0);
        const float al1 = __expf(m1v - mn1);
        m0v = mn0; m1v = mn1;
        l0 = l0 * al0 + sum0;
        l1 = l1 * al1 + sum1;
#pragma unroll
        for (int dt = 0; dt < 8; dt++) {
            o[dt][0] *= al0; o[dt][1] *= al0;
            o[dt][2] *= al1; o[dt][3] *= al1;
        }

        // ---- O += P V : P frags packed straight from C-frags ----
#pragma unroll
        for (int kt = 0; kt < 4; kt++) {
            uint32_t ap[4];
            ap[0] = packh2(sc[2 * kt][0],     sc[2 * kt][1]);
            ap[1] = packh2(sc[2 * kt][2],     sc[2 * kt][3]);
            ap[2] = packh2(sc[2 * kt + 1][0], sc[2 * kt + 1][1]);
            ap[3] = packh2(sc[2 * kt + 1][2], sc[2 * kt + 1][3]);
#pragma unroll
            for (int d2 = 0; d2 < 4; d2++) {
                uint32_t vb[4];
                ldsm4t(vb, voff + (kt * 16 * QS_ + d2 * 16 + vlb) * 2);
                mma_f16(o[2 * d2],     ap, &vb[0], o[2 * d2]);
                mma_f16(o[2 * d2 + 1], ap, &vb[2], o[2 * d2 + 1]);
            }
        }
    }

    // ---- epilogue ----
    const float inv0 = 1.f / l0, inv1 = 1.f / l1;
    const int row = q0 + wq + g;
#pragma unroll
    for (int dt = 0; dt < 8; dt++) {
        const int col = h * 64 + dt * 8 + 2 * q;
        __half2 v0 = __floats2half2_rn(o[dt][0] * inv0, o[dt][1] * inv0);
        __half2 v1 = __floats2half2_rn(o[dt][2] * inv1, o[dt][3] * inv1);
        *(__half2*)&g_ctxh[((size_t)b * N_ + row) * H_ + col] = v0;
        *(__half2*)&g_ctxh[((size_t)b * N_ + row + 8) * H_ + col] = v1;
    }
}

// ===================================================================
// LayerNorm + gather.
// ===================================================================
__global__ __launch_bounds__(256) void ln_kernel(
    const float* __restrict__ gamma, const float* __restrict__ beta,
    const int* __restrict__ conv_len, float* __restrict__ out)
{
    const int row = blockIdx.x;
    const int tid = threadIdx.x;
    const float4 v = *(const float4*)&g_y[(size_t)row * H_ + tid * 4];

    float s = v.x + v.y + v.z + v.w;
    float sq = v.x * v.x + v.y * v.y + v.z * v.z + v.w * v.w;

    __shared__ float rsum[8], rsq[8];
    const int lane = tid & 31, wid = tid >> 5;
#pragma unroll
    for (int off = 16; off; off >>= 1) {
        s += __shfl_xor_sync(0xffffffffu, s, off);
        sq += __shfl_xor_sync(0xffffffffu, sq, off);
    }
    if (lane == 0) { rsum[wid] = s; rsq[wid] = sq; }
    __syncthreads();
    if (tid == 0) {
        float a = 0.f, b2 = 0.f;
#pragma unroll
        for (int i = 0; i < 8; i++) { a += rsum[i]; b2 += rsq[i]; }
        rsum[0] = a; rsq[0] = b2;
    }
    __syncthreads();
    const float mean = rsum[0] * (1.0f / H_);
    const float var = rsq[0] * (1.0f / H_) - mean * mean;
    const float rstd = rsqrtf(var + 1e-12f);

    const float4 g = *(const float4*)&gamma[tid * 4];
    const float4 bt = *(const float4*)&beta[tid * 4];
    float4 r = make_float4((v.x - mean) * rstd * g.x + bt.x,
                           (v.y - mean) * rstd * g.y + bt.y,
                           (v.z - mean) * rstd * g.z + bt.z,
                           (v.w - mean) * rstd * g.w + bt.w);
    *(float4*)&out[(size_t)row * H_ + tid * 4] = r;

    const int bi = row >> 10, n = row & 1023;
    const int base = 6 * conv_len[bi];
    if (n == base + 3)
        *(float4*)&out[CTXN_ + (size_t)bi * H_ + tid * 4] = r;
    if (n == base + 2)
        *(float4*)&out[CTXN_ + (size_t)B_ * H_ + (size_t)bi * H_ + tid * 4] = r;
}

// ===================================================================
extern "C" void kernel_launch(void* const* d_in, const int* in_sizes, int n_in,
                              void* d_out, int out_size)
{
    const float* hs        = (const float*)d_in[0];
    const int*   role_mask = (const int*)d_in[1];
    const int*   conv_len  = (const int*)d_in[2];
    const float* Wq = (const float*)d_in[3];
    const float* bq = (const float*)d_in[4];
    const float* Wk = (const float*)d_in[5];
    const float* bk = (const float*)d_in[6];
    const float* Wv = (const float*)d_in[7];
    const float* bv = (const float*)d_in[8];
    const float* Wo = (const float*)d_in[9];
    const float* bo = (const float*)d_in[10];
    const float* gamma = (const float*)d_in[11];
    const float* beta  = (const float*)d_in[12];
    float* out = (float*)d_out;

    cvt_inputs<<<(int)((CTXN_ + 4 * (1u << 20)) / (256 * 8)), 256>>>(hs, Wq, Wk, Wv, Wo);
    pack_mask<<<(B_ * N_ * 32) / 256, 256>>>(role_mask);
    gemm_h<0><<<dim3(H_ / 128, M_ / 128, 3), 256>>>(bq, bk, bv, nullptr);
    attn_h<<<dim3(N_ / 128, B_ * HEADS_), 256>>>();
    gemm_h<1><<<dim3(H_ / 128, M_ / 128), 256>>>(bo, nullptr, nullptr, hs);
    ln_kernel<<<M_, 256>>>(gamma, beta, conv_len, out);
}

// round 13
// speedup vs baseline: 1.0017x; 1.0017x over previous
#include <cuda_runtime.h>
#include <cuda_fp16.h>
#include <math.h>
#include <stdint.h>

#define B_      8
#define N_      1024
#define H_      1024
#define HEADS_  16
#define DH_     64
#define M_      (B_ * N_)          // 8192
#define CTXN_   ((size_t)M_ * H_)  // 8388608

// -------- scratch (device globals; no allocation allowed) --------
__device__ __half g_Xh[(size_t)M_ * H_];                 // hidden in half
__device__ __half g_Wh[4][(size_t)H_ * H_];              // Wq,Wk,Wv,Wo in half
__device__ __half g_Qh[(size_t)B_ * HEADS_ * N_ * DH_];  // head-split [bh][n][64]
__device__ __half g_Kh[(size_t)B_ * HEADS_ * N_ * DH_];
__device__ __half g_Vh[(size_t)B_ * HEADS_ * N_ * DH_];
__device__ __half g_ctxh[(size_t)M_ * H_];
__device__ float  g_y[(size_t)M_ * H_];
__device__ unsigned g_maskbits[(size_t)B_ * N_ * (N_ / 32)];   // 1MB bitmask

// ---------------- mma / ldmatrix helpers ----------------
__device__ __forceinline__ void mma_f16(float* d, const uint32_t* a, const uint32_t* b, const float* c) {
    asm volatile(
        "mma.sync.aligned.m16n8k16.row.col.f32.f16.f16.f32 "
        "{%0,%1,%2,%3}, {%4,%5,%6,%7}, {%8,%9}, {%10,%11,%12,%13};\n"
        : "=f"(d[0]), "=f"(d[1]), "=f"(d[2]), "=f"(d[3])
        : "r"(a[0]), "r"(a[1]), "r"(a[2]), "r"(a[3]),
          "r"(b[0]), "r"(b[1]),
          "f"(c[0]), "f"(c[1]), "f"(c[2]), "f"(c[3]));
}

__device__ __forceinline__ void ldsm4(uint32_t* r, uint32_t addr) {
    asm volatile("ldmatrix.sync.aligned.m8n8.x4.shared.b16 {%0,%1,%2,%3}, [%4];\n"
        : "=r"(r[0]), "=r"(r[1]), "=r"(r[2]), "=r"(r[3]) : "r"(addr));
}
__device__ __forceinline__ void ldsm4t(uint32_t* r, uint32_t addr) {
    asm volatile("ldmatrix.sync.aligned.m8n8.x4.trans.shared.b16 {%0,%1,%2,%3}, [%4];\n"
        : "=r"(r[0]), "=r"(r[1]), "=r"(r[2]), "=r"(r[3]) : "r"(addr));
}
__device__ __forceinline__ uint32_t packh2(float lo, float hi) {
    __half2 h = __floats2half2_rn(lo, hi);
    return *(uint32_t*)&h;
}
__device__ __forceinline__ uint32_t smem_u32(const void* p) {
    return (uint32_t)__cvta_generic_to_shared(p);
}

// ===================================================================
// Kernel A: convert X + 4 weights to half. 8 elems/thread.
// ===================================================================
__global__ __launch_bounds__(256) void cvt_inputs(
    const float* __restrict__ hs,
    const float* __restrict__ wq, const float* __restrict__ wk,
    const float* __restrict__ wv, const float* __restrict__ wo)
{
    size_t gid = ((size_t)blockIdx.x * 256 + threadIdx.x) * 8;
    const float* src;
    __half* dst;
    size_t off;
    if (gid < CTXN_) { src = hs; dst = g_Xh; off = gid; }
    else {
        size_t r = gid - CTXN_;
        int seg = (int)(r >> 20);
        off = r & ((1u << 20) - 1);
        src = (seg == 0) ? wq : (seg == 1) ? wk : (seg == 2) ? wv : wo;
        dst = g_Wh[seg];
    }
    float4 a = *(const float4*)(src + off);
    float4 b = *(const float4*)(src + off + 4);
    uint4 u;
    u.x = packh2(a.x, a.y); u.y = packh2(a.z, a.w);
    u.z = packh2(b.x, b.y); u.w = packh2(b.z, b.w);
    *(uint4*)(dst + off) = u;
}

// ===================================================================
// Kernel B: pack role_mask into bitmask.
// ===================================================================
__global__ __launch_bounds__(256) void pack_mask(const int* __restrict__ mask)
{
    const int gid = blockIdx.x * 256 + threadIdx.x;
    const int4* p = (const int4*)(mask + (size_t)gid * 32);
    uint32_t bits = 0;
#pragma unroll
    for (int i = 0; i < 8; i++) {
        int4 v = p[i];
        bits |= (uint32_t)(v.x != 0) << (i * 4 + 0);
        bits |= (uint32_t)(v.y != 0) << (i * 4 + 1);
        bits |= (uint32_t)(v.z != 0) << (i * 4 + 2);
        bits |= (uint32_t)(v.w != 0) << (i * 4 + 3);
    }
    g_maskbits[gid] = bits;
}

// ===================================================================
// fp16 tensor-core GEMM: 128x128 tile, BK=16, 8 warps (2x4), warp 64x32.
// MODE 0: QKV (z selects W/bias/out), head-split half output.
// MODE 1: out proj: acc + bias + residual -> g_y (fp32).
// ===================================================================
#define AS_ 24
#define BS_ 136
#define A_BUF_B (128 * AS_ * 2)   // 6144 bytes
#define B_BUF_B (16 * BS_ * 2)    // 4352 bytes

template<int MODE>
__global__ __launch_bounds__(256, 2) void gemm_h(
    const float* __restrict__ b0p, const float* __restrict__ b1p,
    const float* __restrict__ b2p, const float* __restrict__ hidden)
{
    __shared__ __align__(16) __half sA[2][128 * AS_];
    __shared__ __align__(16) __half sB[2][16 * BS_];

    const __half* A;
    const __half* W;
    const float* bias;
    if (MODE == 0) {
        A = g_Xh;
        W = g_Wh[blockIdx.z];
        bias = (blockIdx.z == 0) ? b0p : (blockIdx.z == 1) ? b1p : b2p;
    } else {
        A = g_ctxh;
        W = g_Wh[3];
        bias = b0p;
    }

    const int tid = threadIdx.x;
    const int warp = tid >> 5, lane = tid & 31;
    const int g = lane >> 2, q = lane & 3;
    const int wm = (warp >> 2) * 64, wn = (warp & 3) * 32;
    const int m0 = blockIdx.y * 128, n0 = blockIdx.x * 128;

    const int arow = tid >> 1, acol = (tid & 1) * 8;
    const int brow = tid >> 4, bcol = (tid & 15) * 8;

    uint4 ra, rb;
    auto LDG = [&](int k0) {
        ra = *(const uint4*)&A[(size_t)(m0 + arow) * H_ + k0 + acol];
        rb = *(const uint4*)&W[(size_t)(k0 + brow) * H_ + n0 + bcol];
    };
    auto STS = [&](int st) {
        *(uint4*)&sA[st][arow * AS_ + acol] = ra;
        *(uint4*)&sB[st][brow * BS_ + bcol] = rb;
    };

    const uint32_t sAb = smem_u32(&sA[0][0]);
    const uint32_t sBb = smem_u32(&sB[0][0]);
    const int la = lane & 15, lb = lane >> 4;
    const uint32_t aoff = ((wm + la) * AS_ + lb * 8) * 2;
    const uint32_t boff = (la * BS_ + wn + lb * 8) * 2;

    float acc[4][4][4];
#pragma unroll
    for (int mt = 0; mt < 4; mt++)
#pragma unroll
        for (int nt = 0; nt < 4; nt++)
#pragma unroll
            for (int j = 0; j < 4; j++) acc[mt][nt][j] = 0.f;

    LDG(0); STS(0);
    __syncthreads();

    for (int kt = 0; kt < 64; kt++) {
        const int cur = kt & 1;
        if (kt < 63) LDG((kt + 1) * 16);

        const uint32_t bufA = sAb + cur * A_BUF_B;
        const uint32_t bufB = sBb + cur * B_BUF_B;
        uint32_t a[4][4], b[2][4];
#pragma unroll
        for (int mt = 0; mt < 4; mt++)
            ldsm4(a[mt], bufA + aoff + mt * (16 * AS_ * 2));
#pragma unroll
        for (int n2 = 0; n2 < 2; n2++)
            ldsm4t(b[n2], bufB + boff + n2 * 32);
#pragma unroll
        for (int mt = 0; mt < 4; mt++)
#pragma unroll
            for (int nt = 0; nt < 4; nt++)
                mma_f16(acc[mt][nt], a[mt], &b[nt >> 1][(nt & 1) * 2], acc[mt][nt]);

        if (kt < 63) STS(cur ^ 1);
        __syncthreads();
    }

    // ---------------- epilogue ----------------
    if (MODE == 0) {
        __half* out = (blockIdx.z == 0) ? g_Qh : (blockIdx.z == 1) ? g_Kh : g_Vh;
        const int bi = m0 >> 10;
#pragma unroll
        for (int mt = 0; mt < 4; mt++) {
            const int row = m0 + wm + mt * 16 + g;
            const int n = row & 1023;
#pragma unroll
            for (int nt = 0; nt < 4; nt++) {
                const int col = n0 + wn + nt * 8 + 2 * q;
                const int head = col >> 6, d = col & 63;
                const float bb0 = __ldg(&bias[col]), bb1 = __ldg(&bias[col + 1]);
                __half2 v0 = __floats2half2_rn(acc[mt][nt][0] + bb0, acc[mt][nt][1] + bb1);
                __half2 v1 = __floats2half2_rn(acc[mt][nt][2] + bb0, acc[mt][nt][3] + bb1);
                *(__half2*)&out[(((size_t)bi * HEADS_ + head) * N_ + n) * DH_ + d] = v0;
                *(__half2*)&out[(((size_t)bi * HEADS_ + head) * N_ + n + 8) * DH_ + d] = v1;
            }
        }
    } else {
#pragma unroll
        for (int mt = 0; mt < 4; mt++) {
            const int row = m0 + wm + mt * 16 + g;
#pragma unroll
            for (int nt = 0; nt < 4; nt++) {
                const int col = n0 + wn + nt * 8 + 2 * q;
                const float bb0 = __ldg(&bias[col]), bb1 = __ldg(&bias[col + 1]);
                size_t o0 = (size_t)row * H_ + col;
                size_t o1 = (size_t)(row + 8) * H_ + col;
                float2 h0 = *(const float2*)&hidden[o0];
                float2 h1 = *(const float2*)&hidden[o1];
                *(float2*)&g_y[o0] = make_float2(acc[mt][nt][0] + bb0 + h0.x, acc[mt][nt][1] + bb1 + h0.y);
                *(float2*)&g_y[o1] = make_float2(acc[mt][nt][2] + bb0 + h1.x, acc[mt][nt][3] + bb1 + h1.y);
            }
        }
    }
}

// ===================================================================
// fp16 flash attention. q-tile 128, 8 warps (16 q-rows each), k-chunk 64.
// P C-frags repack directly into A-frags (no shuffles).
// ===================================================================
#define QS_ 72
__global__ __launch_bounds__(256, 2) void attn_h()
{
    __shared__ __align__(16) __half sQ[128 * QS_];
    __shared__ __align__(16) __half sK[64 * QS_];
    __shared__ __align__(16) __half sV[64 * QS_];

    const int tid = threadIdx.x;
    const int warp = tid >> 5, lane = tid & 31;
    const int g = lane >> 2, q = lane & 3;
    const int wq = warp * 16;

    const int bh = blockIdx.y;
    const int b = bh >> 4, h = bh & 15;
    const int q0 = blockIdx.x * 128;

    const __half* Qg = g_Qh + (size_t)bh * N_ * DH_;
    const __half* Kg = g_Kh + (size_t)bh * N_ * DH_;
    const __half* Vg = g_Vh + (size_t)bh * N_ * DH_;

    const int lrow = tid >> 3, lcol = (tid & 7) * 8;

    // Q tile 128x64
#pragma unroll
    for (int i = 0; i < 4; i++) {
        int r = i * 32 + lrow;
        uint4 v = *(const uint4*)&Qg[(size_t)(q0 + r) * DH_ + lcol];
        *(uint4*)&sQ[r * QS_ + lcol] = v;
    }
    auto loadKV = [&](int k0) {
#pragma unroll
        for (int i = 0; i < 2; i++) {
            int r = i * 32 + lrow;
            uint4 kv = *(const uint4*)&Kg[(size_t)(k0 + r) * DH_ + lcol];
            *(uint4*)&sK[r * QS_ + lcol] = kv;
            uint4 vv = *(const uint4*)&Vg[(size_t)(k0 + r) * DH_ + lcol];
            *(uint4*)&sV[r * QS_ + lcol] = vv;
        }
    };
    loadKV(0);
    __syncthreads();

    const uint32_t sQb = smem_u32(sQ), sKb = smem_u32(sK), sVb = smem_u32(sV);
    const int la = lane & 15, lb = lane >> 4;

    // Q frags once (constant over k-loop)
    uint32_t aq[4][4];
    {
        const uint32_t base = sQb + ((wq + la) * QS_ + lb * 8) * 2;
#pragma unroll
        for (int ks = 0; ks < 4; ks++) ldsm4(aq[ks], base + ks * 32);
    }

    const int kla = (lane >> 4) * 8 + (lane & 7);        // K frag row part
    const int klb = ((lane >> 3) & 1) * 8;               // K frag col part
    const int vla = ((lane >> 3) & 1) * 8 + (lane & 7);  // V frag row part
    const int vlb = (lane >> 4) * 8;                     // V frag col part
    const uint32_t koff = sKb + (kla * QS_ + klb) * 2;
    const uint32_t voff = sVb + (vla * QS_) * 2;

    const uint32_t* mrow0 = &g_maskbits[((size_t)(b << 10) + q0 + wq + g) * 32];
    const uint32_t* mrow1 = mrow0 + 8 * 32;

    float m0v = -INFINITY, m1v = -INFINITY, l0 = 0.f, l1 = 0.f;
    float o[8][4];
#pragma unroll
    for (int dt = 0; dt < 8; dt++)
#pragma unroll
        for (int j = 0; j < 4; j++) o[dt][j] = 0.f;

    for (int c = 0; c < 16; c++) {
        const int k0 = c * 64;
        if (c > 0) {
            __syncthreads();
            loadKV(k0);
            __syncthreads();
        }
        const int kw = k0 >> 5;
        const uint32_t w0a = __ldg(mrow0 + kw), w0b = __ldg(mrow0 + kw + 1);
        const uint32_t w1a = __ldg(mrow1 + kw), w1b = __ldg(mrow1 + kw + 1);

        // ---- S = Q K^T ----
        float sc[8][4];
#pragma unroll
        for (int nt = 0; nt < 8; nt++)
#pragma unroll
            for (int j = 0; j < 4; j++) sc[nt][j] = 0.f;

#pragma unroll
        for (int ks = 0; ks < 4; ks++) {
#pragma unroll
            for (int kg = 0; kg < 4; kg++) {
                uint32_t kb[4];
                ldsm4(kb, koff + (kg * 16 * QS_ + ks * 16) * 2);
                mma_f16(sc[2 * kg],     aq[ks], &kb[0], sc[2 * kg]);
                mma_f16(sc[2 * kg + 1], aq[ks], &kb[2], sc[2 * kg + 1]);
            }
        }

        // ---- mask + online softmax ----
        float mx0 = -INFINITY, mx1 = -INFINITY;
#pragma unroll
        for (int nt = 0; nt < 8; nt++) {
            const uint32_t ws0 = (nt < 4) ? w0a : w0b;
            const uint32_t ws1 = (nt < 4) ? w1a : w1b;
            const int bb = (nt & 3) * 8 + 2 * q;
            sc[nt][0] = ((ws0 >> bb) & 1u)       ? sc[nt][0] * 0.125f : -1e9f;
            sc[nt][1] = ((ws0 >> (bb + 1)) & 1u) ? sc[nt][1] * 0.125f : -1e9f;
            sc[nt][2] = ((ws1 >> bb) & 1u)       ? sc[nt][2] * 0.125f : -1e9f;
            sc[nt][3] = ((ws1 >> (bb + 1)) & 1u) ? sc[nt][3] * 0.125f : -1e9f;
            mx0 = fmaxf(mx0, fmaxf(sc[nt][0], sc[nt][1]));
            mx1 = fmaxf(mx1, fmaxf(sc[nt][2], sc[nt][3]));
        }
        mx0 = fmaxf(mx0, __shfl_xor_sync(0xffffffffu, mx0, 1));
        mx0 = fmaxf(mx0, __shfl_xor_sync(0xffffffffu, mx0, 2));
        mx1 = fmaxf(mx1, __shfl_xor_sync(0xffffffffu, mx1, 1));
        mx1 = fmaxf(mx1, __shfl_xor_sync(0xffffffffu, mx1, 2));

        const float mn0 = fmaxf(m0v, mx0);
        const float mn1 = fmaxf(m1v, mx1);
        float sum0 = 0.f, sum1 = 0.f;
#pragma unroll
        for (int nt = 0; nt < 8; nt++) {
            sc[nt][0] = __expf(sc[nt][0] - mn0);
            sc[nt][1] = __expf(sc[nt][1] - mn0);
            sc[nt][2] = __expf(sc[nt][2] - mn1);
            sc[nt][3] = __expf(sc[nt][3] - mn1);
            sum0 += sc[nt][0] + sc[nt][1];
            sum1 += sc[nt][2] + sc[nt][3];
        }
        sum0 += __shfl_xor_sync(0xffffffffu, sum0, 1);
        sum0 += __shfl_xor_sync(0xffffffffu, sum0, 2);
        sum1 += __shfl_xor_sync(0xffffffffu, sum1, 1);
        sum1 += __shfl_xor_sync(0xffffffffu, sum1, 2);

        const float al0 = __expf(m0v - mn0);
        const float al1 = __expf(m1v - mn1);
        m0v = mn0; m1v = mn1;
        l0 = l0 * al0 + sum0;
        l1 = l1 * al1 + sum1;
#pragma unroll
        for (int dt = 0; dt < 8; dt++) {
            o[dt][0] *= al0; o[dt][1] *= al0;
            o[dt][2] *= al1; o[dt][3] *= al1;
        }

        // ---- O += P V : P frags packed straight from C-frags ----
#pragma unroll
        for (int kt = 0; kt < 4; kt++) {
            uint32_t ap[4];
            ap[0] = packh2(sc[2 * kt][0],     sc[2 * kt][1]);
            ap[1] = packh2(sc[2 * kt][2],     sc[2 * kt][3]);
            ap[2] = packh2(sc[2 * kt + 1][0], sc[2 * kt + 1][1]);
            ap[3] = packh2(sc[2 * kt + 1][2], sc[2 * kt + 1][3]);
#pragma unroll
            for (int d2 = 0; d2 < 4; d2++) {
                uint32_t vb[4];
                ldsm4t(vb, voff + (kt * 16 * QS_ + d2 * 16 + vlb) * 2);
                mma_f16(o[2 * d2],     ap, &vb[0], o[2 * d2]);
                mma_f16(o[2 * d2 + 1], ap, &vb[2], o[2 * d2 + 1]);
            }
        }
    }

    // ---- epilogue ----
    const float inv0 = 1.f / l0, inv1 = 1.f / l1;
    const int row = q0 + wq + g;
#pragma unroll
    for (int dt = 0; dt < 8; dt++) {
        const int col = h * 64 + dt * 8 + 2 * q;
        __half2 v0 = __floats2half2_rn(o[dt][0] * inv0, o[dt][1] * inv0);
        __half2 v1 = __floats2half2_rn(o[dt][2] * inv1, o[dt][3] * inv1);
        *(__half2*)&g_ctxh[((size_t)b * N_ + row) * H_ + col] = v0;
        *(__half2*)&g_ctxh[((size_t)b * N_ + row + 8) * H_ + col] = v1;
    }
}

// ===================================================================
// LayerNorm + gather.
// ===================================================================
__global__ __launch_bounds__(256) void ln_kernel(
    const float* __restrict__ gamma, const float* __restrict__ beta,
    const int* __restrict__ conv_len, float* __restrict__ out)
{
    const int row = blockIdx.x;
    const int tid = threadIdx.x;
    const float4 v = *(const float4*)&g_y[(size_t)row * H_ + tid * 4];

    float s = v.x + v.y + v.z + v.w;
    float sq = v.x * v.x + v.y * v.y + v.z * v.z + v.w * v.w;

    __shared__ float rsum[8], rsq[8];
    const int lane = tid & 31, wid = tid >> 5;
#pragma unroll
    for (int off = 16; off; off >>= 1) {
        s += __shfl_xor_sync(0xffffffffu, s, off);
        sq += __shfl_xor_sync(0xffffffffu, sq, off);
    }
    if (lane == 0) { rsum[wid] = s; rsq[wid] = sq; }
    __syncthreads();
    if (tid == 0) {
        float a = 0.f, b2 = 0.f;
#pragma unroll
        for (int i = 0; i < 8; i++) { a += rsum[i]; b2 += rsq[i]; }
        rsum[0] = a; rsq[0] = b2;
    }
    __syncthreads();
    const float mean = rsum[0] * (1.0f / H_);
    const float var = rsq[0] * (1.0f / H_) - mean * mean;
    const float rstd = rsqrtf(var + 1e-12f);

    const float4 g = *(const float4*)&gamma[tid * 4];
    const float4 bt = *(const float4*)&beta[tid * 4];
    float4 r = make_float4((v.x - mean) * rstd * g.x + bt.x,
                           (v.y - mean) * rstd * g.y + bt.y,
                           (v.z - mean) * rstd * g.z + bt.z,
                           (v.w - mean) * rstd * g.w + bt.w);
    *(float4*)&out[(size_t)row * H_ + tid * 4] = r;

    const int bi = row >> 10, n = row & 1023;
    const int base = 6 * conv_len[bi];
    if (n == base + 3)
        *(float4*)&out[CTXN_ + (size_t)bi * H_ + tid * 4] = r;
    if (n == base + 2)
        *(float4*)&out[CTXN_ + (size_t)B_ * H_ + (size_t)bi * H_ + tid * 4] = r;
}

// ===================================================================
extern "C" void kernel_launch(void* const* d_in, const int* in_sizes, int n_in,
                              void* d_out, int out_size)
{
    const float* hs        = (const float*)d_in[0];
    const int*   role_mask = (const int*)d_in[1];
    const int*   conv_len  = (const int*)d_in[2];
    const float* Wq = (const float*)d_in[3];
    const float* bq = (const float*)d_in[4];
    const float* Wk = (const float*)d_in[5];
    const float* bk = (const float*)d_in[6];
    const float* Wv = (const float*)d_in[7];
    const float* bv = (const float*)d_in[8];
    const float* Wo = (const float*)d_in[9];
    const float* bo = (const float*)d_in[10];
    const float* gamma = (const float*)d_in[11];
    const float* beta  = (const float*)d_in[12];
    float* out = (float*)d_out;

    cvt_inputs<<<(int)((CTXN_ + 4 * (1u << 20)) / (256 * 8)), 256>>>(hs, Wq, Wk, Wv, Wo);
    pack_mask<<<(B_ * N_ * 32) / 256, 256>>>(role_mask);
    gemm_h<0><<<dim3(H_ / 128, M_ / 128, 3), 256>>>(bq, bk, bv, nullptr);
    attn_h<<<dim3(N_ / 128, B_ * HEADS_), 256>>>();
    gemm_h<1><<<dim3(H_ / 128, M_ / 128), 256>>>(bo, nullptr, nullptr, hs);
    ln_kernel<<<M_, 256>>>(gamma, beta, conv_len, out);
}